// round 15
// baseline (speedup 1.0000x reference)
#include <cuda_runtime.h>
#include <cuda_fp16.h>

// Channel-last fp16 copies of all 4 img tensors.
// Half-element offsets: s512: 0 | s256: 67,108,864 | s128: 83,886,080 |
// s64: 88,080,384. Total 89,128,960 halfs.
__device__ __half g_timg[89128960];

// Per-scale block counts (256 threads, 2 threads/pixel, 128 px/block):
//   s512: 32768 (2048/batch) | s256: 8192 | s128: 2048 | s64: 512

// ---------------------------------------------------------------------------
// Transpose [B,C,H,W] fp32 -> [B,H,W,C] fp16 (proven path, unchanged).
// ---------------------------------------------------------------------------
template <unsigned LG>
__device__ __forceinline__ void do_transpose(const float* __restrict__ img,
                                             __half* __restrict__ timg,
                                             unsigned bx) {
    const unsigned t  = bx * 256u + threadIdx.x;
    const unsigned g  = t & 1u;
    const unsigned p  = t >> 1;
    constexpr unsigned HW = 1u << (2u * LG);
    const unsigned b  = p >> (2u * LG);

    const float* src = img + (size_t)p + (size_t)(b * 15u + g * 8u) * HW;
    float v[8];
#pragma unroll
    for (int k = 0; k < 8; k++) v[k] = __ldcs(src + (size_t)k * HW);

    __half2 h0 = __floats2half2_rn(v[0], v[1]);
    __half2 h1 = __floats2half2_rn(v[2], v[3]);
    __half2 h2 = __floats2half2_rn(v[4], v[5]);
    __half2 h3 = __floats2half2_rn(v[6], v[7]);
    uint4 o;
    o.x = *reinterpret_cast<unsigned*>(&h0);
    o.y = *reinterpret_cast<unsigned*>(&h1);
    o.z = *reinterpret_cast<unsigned*>(&h2);
    o.w = *reinterpret_cast<unsigned*>(&h3);
    reinterpret_cast<uint4*>(timg)[t] = o;
}

// ---------------------------------------------------------------------------
// Gather (proven path): 2 threads per pixel (8 channels each), branchless
// corners (validity folded into weights, clamped indices, 4 unconditional
// LDG.128). R15 change: out stores use __stwt (write-through, no L2
// allocation) so the 356 MB out stream cannot evict L2-resident timg.
//   x = (i-1) + flow_ch0 * 0.5*(W-1)   (width coord)
//   y = (j-1) + flow_ch1 * 0.5*(H-1)   (height coord)
// ---------------------------------------------------------------------------
template <unsigned LG>
__device__ __forceinline__ void do_gather(const float* __restrict__ flow,
                                          const __half* __restrict__ timg,
                                          float* __restrict__ outp,
                                          unsigned bx) {
    const unsigned t     = bx * 256u + threadIdx.x;
    const unsigned chalf = t & 1u;
    const unsigned p     = t >> 1;
    constexpr unsigned W  = 1u << LG;
    constexpr unsigned HW = 1u << (2u * LG);
    constexpr int      Wi = (int)W;
    const unsigned j   = p & (W - 1u);
    const unsigned i   = (p >> LG) & (W - 1u);
    const unsigned b   = p >> (2u * LG);
    const unsigned pix = p & (HW - 1u);

    const float f0 = __ldcs(flow + (size_t)(b * 2u) * HW + pix);
    const float f1 = __ldcs(flow + (size_t)(b * 2u + 1u) * HW + pix);

    constexpr float sc = 0.5f * (float)(W - 1u);
    const float x = (float)((int)i - 1) + f0 * sc;   // width coord
    const float y = (float)((int)j - 1) + f1 * sc;   // height coord

    const float x0f = floorf(x);
    const float y0f = floorf(y);
    const int x0 = (int)x0f, x1 = x0 + 1;
    const int y0 = (int)y0f, y1 = y0 + 1;
    const float fx = x - x0f, fy = y - y0f;

    const float wx1 = (x1 >= 0 && x1 < Wi) ? fx        : 0.0f;
    const float wx0 = (x0 >= 0 && x0 < Wi) ? 1.0f - fx : 0.0f;
    const float wy1 = (y1 >= 0 && y1 < Wi) ? fy        : 0.0f;
    const float wy0 = (y0 >= 0 && y0 < Wi) ? 1.0f - fy : 0.0f;

    const unsigned x0c = (unsigned)min(max(x0, 0), Wi - 1);
    const unsigned x1c = (unsigned)min(max(x1, 0), Wi - 1);
    const unsigned y0c = (unsigned)min(max(y0, 0), Wi - 1);
    const unsigned y1c = (unsigned)min(max(y1, 0), Wi - 1);

    const uint4* base = reinterpret_cast<const uint4*>(timg)
                        + (size_t)(b * HW) * 2u + chalf;
    const uint4 r00 = __ldg(base + (size_t)(y0c * W + x0c) * 2u);
    const uint4 r01 = __ldg(base + (size_t)(y0c * W + x1c) * 2u);
    const uint4 r10 = __ldg(base + (size_t)(y1c * W + x0c) * 2u);
    const uint4 r11 = __ldg(base + (size_t)(y1c * W + x1c) * 2u);

    const float w00 = wy0 * wx0, w01 = wy0 * wx1;
    const float w10 = wy1 * wx0, w11 = wy1 * wx1;

    float acc[8];
    const unsigned c00[4] = {r00.x, r00.y, r00.z, r00.w};
    const unsigned c01[4] = {r01.x, r01.y, r01.z, r01.w};
    const unsigned c10[4] = {r10.x, r10.y, r10.z, r10.w};
    const unsigned c11[4] = {r11.x, r11.y, r11.z, r11.w};
#pragma unroll
    for (int q = 0; q < 4; q++) {
        float2 v00 = __half22float2(*reinterpret_cast<const __half2*>(&c00[q]));
        float2 v01 = __half22float2(*reinterpret_cast<const __half2*>(&c01[q]));
        float2 v10 = __half22float2(*reinterpret_cast<const __half2*>(&c10[q]));
        float2 v11 = __half22float2(*reinterpret_cast<const __half2*>(&c11[q]));
        acc[2 * q + 0] = w00 * v00.x + w01 * v01.x + w10 * v10.x + w11 * v11.x;
        acc[2 * q + 1] = w00 * v00.y + w01 * v01.y + w10 * v10.y + w11 * v11.y;
    }

    // out layout [B,C,H,W]; write-through -> no L2 allocation/pollution.
    float* ob = outp + (size_t)(b * 16u + chalf * 8u) * HW + pix;
#pragma unroll
    for (int q = 0; q < 8; q++) {
        __stwt(ob + (size_t)q * HW, acc[q]);
    }
}

// Small-scale dispatchers (10752 blocks: s256 [0,8192) | s128 [8192,10240) |
// s64 [10240,10752)).
__device__ __forceinline__ void tsmall(unsigned bx,
                                       const float* im1, const float* im2,
                                       const float* im3) {
    if (bx < 8192u)       do_transpose<8>(im1, g_timg + 67108864u, bx);
    else if (bx < 10240u) do_transpose<7>(im2, g_timg + 83886080u, bx - 8192u);
    else                  do_transpose<6>(im3, g_timg + 88080384u, bx - 10240u);
}
__device__ __forceinline__ void gsmall(unsigned bx,
                                       const float* fl1, const float* fl2,
                                       const float* fl3, float* out) {
    if (bx < 8192u)       do_gather<8>(fl1, g_timg + 67108864u, out + 67108864u, bx);
    else if (bx < 10240u) do_gather<7>(fl2, g_timg + 83886080u, out + 83886080u, bx - 8192u);
    else                  do_gather<6>(fl3, g_timg + 88080384u, out + 88080384u, bx - 10240u);
}

// ---------------------------------------------------------------------------
// K1 (unchanged): ALL transposes. T512 blocks [0,32768) ascending, small
// transposes last -> small timg + late s512 batches L2-hot at K2 start.
// Grid = 43520. Pure DRAM streaming.
// ---------------------------------------------------------------------------
__global__ void k1_transpose_all(const float* __restrict__ im0,
                                 const float* __restrict__ im1,
                                 const float* __restrict__ im2,
                                 const float* __restrict__ im3) {
    const unsigned bx = blockIdx.x;
    if (bx < 32768u) do_transpose<9>(im0, g_timg, bx);
    else             tsmall(bx - 32768u, im1, im2, im3);
}

// ---------------------------------------------------------------------------
// K2 (unchanged schedule): ALL gathers, 3:1 interleave (G512 : small). G512
// in DESCENDING batch order (batch 15 first = most recently transposed,
// L2-resident). 2048 blocks per batch. grps = 10923, grid = 43692.
// ---------------------------------------------------------------------------
__global__ void k2_gather_all(const float* __restrict__ fl0,
                              const float* __restrict__ fl1,
                              const float* __restrict__ fl2,
                              const float* __restrict__ fl3,
                              float* __restrict__ out) {
    const unsigned bx   = blockIdx.x;
    const unsigned lane = bx & 3u;
    const unsigned grp  = bx >> 2;
    if (lane < 3u) {
        const unsigned gbx = grp * 3u + lane;
        if (gbx < 32768u) {
            const unsigned bb  = 15u - (gbx >> 11);   // descending batch
            const unsigned blk = gbx & 2047u;
            do_gather<9>(fl0, g_timg, out, bb * 2048u + blk);
        }
    } else {
        if (grp < 10752u) gsmall(grp, fl1, fl2, fl3, out);
    }
}

// ---------------------------------------------------------------------------
// Inputs (metadata order): img0, flow0, img1, flow1, img2, flow2, img3, flow3.
// ---------------------------------------------------------------------------
extern "C" void kernel_launch(void* const* d_in, const int* in_sizes, int n_in,
                              void* d_out, int out_size) {
    (void)in_sizes; (void)n_in; (void)out_size;
    const float* im0 = (const float*)d_in[0];
    const float* fl0 = (const float*)d_in[1];
    const float* im1 = (const float*)d_in[2];
    const float* fl1 = (const float*)d_in[3];
    const float* im2 = (const float*)d_in[4];
    const float* fl2 = (const float*)d_in[5];
    const float* im3 = (const float*)d_in[6];
    const float* fl3 = (const float*)d_in[7];
    float* out = (float*)d_out;

    k1_transpose_all<<<43520, 256>>>(im0, im1, im2, im3);
    k2_gather_all<<<43692, 256>>>(fl0, fl1, fl2, fl3, out);
}

// round 16
// speedup vs baseline: 1.0097x; 1.0097x over previous
#include <cuda_runtime.h>
#include <cuda_fp16.h>

// Channel-last fp16 copies of all 4 img tensors.
// Half-element offsets: s512: 0 | s256: 67,108,864 | s128: 83,886,080 |
// s64: 88,080,384. Total 89,128,960 halfs.
__device__ __half g_timg[89128960];

// Per-scale block counts (256 threads, 2 threads/pixel, 128 px/block):
//   s512: 32768 (2048/batch) | s256: 8192 | s128: 2048 | s64: 512

// ---------------------------------------------------------------------------
// Transpose [B,C,H,W] fp32 -> [B,H,W,C] fp16 (proven path, unchanged).
// ---------------------------------------------------------------------------
template <unsigned LG>
__device__ __forceinline__ void do_transpose(const float* __restrict__ img,
                                             __half* __restrict__ timg,
                                             unsigned bx) {
    const unsigned t  = bx * 256u + threadIdx.x;
    const unsigned g  = t & 1u;
    const unsigned p  = t >> 1;
    constexpr unsigned HW = 1u << (2u * LG);
    const unsigned b  = p >> (2u * LG);

    const float* src = img + (size_t)p + (size_t)(b * 15u + g * 8u) * HW;
    float v[8];
#pragma unroll
    for (int k = 0; k < 8; k++) v[k] = __ldcs(src + (size_t)k * HW);

    __half2 h0 = __floats2half2_rn(v[0], v[1]);
    __half2 h1 = __floats2half2_rn(v[2], v[3]);
    __half2 h2 = __floats2half2_rn(v[4], v[5]);
    __half2 h3 = __floats2half2_rn(v[6], v[7]);
    uint4 o;
    o.x = *reinterpret_cast<unsigned*>(&h0);
    o.y = *reinterpret_cast<unsigned*>(&h1);
    o.z = *reinterpret_cast<unsigned*>(&h2);
    o.w = *reinterpret_cast<unsigned*>(&h3);
    reinterpret_cast<uint4*>(timg)[t] = o;
}

// ---------------------------------------------------------------------------
// Gather (proven R14 path + flow-shuffle dedup): 2 threads per pixel
// (8 channels each). The pair threads (adjacent lanes, same pixel) split the
// flow load -- even lane loads flow ch0, odd lane loads flow ch1 -- and
// exchange via one shfl_xor(1). Halves flow LDG instructions/wavefronts.
// Corners: branchless clamped weights, 4 unconditional LDG.128 (unchanged).
// Streaming __stcs stores on out (unchanged).
//   x = (i-1) + flow_ch0 * 0.5*(W-1)   (width coord)
//   y = (j-1) + flow_ch1 * 0.5*(H-1)   (height coord)
// ---------------------------------------------------------------------------
template <unsigned LG>
__device__ __forceinline__ void do_gather(const float* __restrict__ flow,
                                          const __half* __restrict__ timg,
                                          float* __restrict__ outp,
                                          unsigned bx) {
    const unsigned t     = bx * 256u + threadIdx.x;
    const unsigned chalf = t & 1u;
    const unsigned p     = t >> 1;
    constexpr unsigned W  = 1u << LG;
    constexpr unsigned HW = 1u << (2u * LG);
    constexpr int      Wi = (int)W;
    const unsigned j   = p & (W - 1u);
    const unsigned i   = (p >> LG) & (W - 1u);
    const unsigned b   = p >> (2u * LG);
    const unsigned pix = p & (HW - 1u);

    // Flow dedup: lane parity (== chalf, since t maps 1:1 to lanes) selects
    // which flow channel this thread loads; pair-exchange supplies the other.
    const float fmine = __ldcs(flow + (size_t)(b * 2u + chalf) * HW + pix);
    const float fother = __shfl_xor_sync(0xFFFFFFFFu, fmine, 1);
    const float f0 = chalf ? fother : fmine;   // flow ch0
    const float f1 = chalf ? fmine : fother;   // flow ch1

    constexpr float sc = 0.5f * (float)(W - 1u);
    const float x = (float)((int)i - 1) + f0 * sc;   // width coord
    const float y = (float)((int)j - 1) + f1 * sc;   // height coord

    const float x0f = floorf(x);
    const float y0f = floorf(y);
    const int x0 = (int)x0f, x1 = x0 + 1;
    const int y0 = (int)y0f, y1 = y0 + 1;
    const float fx = x - x0f, fy = y - y0f;

    const float wx1 = (x1 >= 0 && x1 < Wi) ? fx        : 0.0f;
    const float wx0 = (x0 >= 0 && x0 < Wi) ? 1.0f - fx : 0.0f;
    const float wy1 = (y1 >= 0 && y1 < Wi) ? fy        : 0.0f;
    const float wy0 = (y0 >= 0 && y0 < Wi) ? 1.0f - fy : 0.0f;

    const unsigned x0c = (unsigned)min(max(x0, 0), Wi - 1);
    const unsigned x1c = (unsigned)min(max(x1, 0), Wi - 1);
    const unsigned y0c = (unsigned)min(max(y0, 0), Wi - 1);
    const unsigned y1c = (unsigned)min(max(y1, 0), Wi - 1);

    const uint4* base = reinterpret_cast<const uint4*>(timg)
                        + (size_t)(b * HW) * 2u + chalf;
    const uint4 r00 = __ldg(base + (size_t)(y0c * W + x0c) * 2u);
    const uint4 r01 = __ldg(base + (size_t)(y0c * W + x1c) * 2u);
    const uint4 r10 = __ldg(base + (size_t)(y1c * W + x0c) * 2u);
    const uint4 r11 = __ldg(base + (size_t)(y1c * W + x1c) * 2u);

    const float w00 = wy0 * wx0, w01 = wy0 * wx1;
    const float w10 = wy1 * wx0, w11 = wy1 * wx1;

    float acc[8];
    const unsigned c00[4] = {r00.x, r00.y, r00.z, r00.w};
    const unsigned c01[4] = {r01.x, r01.y, r01.z, r01.w};
    const unsigned c10[4] = {r10.x, r10.y, r10.z, r10.w};
    const unsigned c11[4] = {r11.x, r11.y, r11.z, r11.w};
#pragma unroll
    for (int q = 0; q < 4; q++) {
        float2 v00 = __half22float2(*reinterpret_cast<const __half2*>(&c00[q]));
        float2 v01 = __half22float2(*reinterpret_cast<const __half2*>(&c01[q]));
        float2 v10 = __half22float2(*reinterpret_cast<const __half2*>(&c10[q]));
        float2 v11 = __half22float2(*reinterpret_cast<const __half2*>(&c11[q]));
        acc[2 * q + 0] = w00 * v00.x + w01 * v01.x + w10 * v10.x + w11 * v11.x;
        acc[2 * q + 1] = w00 * v00.y + w01 * v01.y + w10 * v10.y + w11 * v11.y;
    }

    // out layout [B,C,H,W]; this thread's channels are [chalf*8, chalf*8+8).
    float* ob = outp + (size_t)(b * 16u + chalf * 8u) * HW + pix;
#pragma unroll
    for (int q = 0; q < 8; q++) {
        __stcs(ob + (size_t)q * HW, acc[q]);
    }
}

// Small-scale dispatchers (10752 blocks: s256 [0,8192) | s128 [8192,10240) |
// s64 [10240,10752)).
__device__ __forceinline__ void tsmall(unsigned bx,
                                       const float* im1, const float* im2,
                                       const float* im3) {
    if (bx < 8192u)       do_transpose<8>(im1, g_timg + 67108864u, bx);
    else if (bx < 10240u) do_transpose<7>(im2, g_timg + 83886080u, bx - 8192u);
    else                  do_transpose<6>(im3, g_timg + 88080384u, bx - 10240u);
}
__device__ __forceinline__ void gsmall(unsigned bx,
                                       const float* fl1, const float* fl2,
                                       const float* fl3, float* out) {
    if (bx < 8192u)       do_gather<8>(fl1, g_timg + 67108864u, out + 67108864u, bx);
    else if (bx < 10240u) do_gather<7>(fl2, g_timg + 83886080u, out + 83886080u, bx - 8192u);
    else                  do_gather<6>(fl3, g_timg + 88080384u, out + 88080384u, bx - 10240u);
}

// ---------------------------------------------------------------------------
// K1 (unchanged): ALL transposes. T512 blocks [0,32768) ascending, small
// transposes last -> small timg + late s512 batches L2-hot at K2 start.
// Grid = 43520. Pure DRAM streaming.
// ---------------------------------------------------------------------------
__global__ void k1_transpose_all(const float* __restrict__ im0,
                                 const float* __restrict__ im1,
                                 const float* __restrict__ im2,
                                 const float* __restrict__ im3) {
    const unsigned bx = blockIdx.x;
    if (bx < 32768u) do_transpose<9>(im0, g_timg, bx);
    else             tsmall(bx - 32768u, im1, im2, im3);
}

// ---------------------------------------------------------------------------
// K2 (unchanged schedule): ALL gathers, 3:1 interleave (G512 : small). G512
// in DESCENDING batch order (batch 15 first = most recently transposed,
// L2-resident). 2048 blocks per batch. grps = 10923, grid = 43692.
// ---------------------------------------------------------------------------
__global__ void k2_gather_all(const float* __restrict__ fl0,
                              const float* __restrict__ fl1,
                              const float* __restrict__ fl2,
                              const float* __restrict__ fl3,
                              float* __restrict__ out) {
    const unsigned bx   = blockIdx.x;
    const unsigned lane = bx & 3u;
    const unsigned grp  = bx >> 2;
    if (lane < 3u) {
        const unsigned gbx = grp * 3u + lane;
        if (gbx < 32768u) {
            const unsigned bb  = 15u - (gbx >> 11);   // descending batch
            const unsigned blk = gbx & 2047u;
            do_gather<9>(fl0, g_timg, out, bb * 2048u + blk);
        }
    } else {
        if (grp < 10752u) gsmall(grp, fl1, fl2, fl3, out);
    }
}

// ---------------------------------------------------------------------------
// Inputs (metadata order): img0, flow0, img1, flow1, img2, flow2, img3, flow3.
// ---------------------------------------------------------------------------
extern "C" void kernel_launch(void* const* d_in, const int* in_sizes, int n_in,
                              void* d_out, int out_size) {
    (void)in_sizes; (void)n_in; (void)out_size;
    const float* im0 = (const float*)d_in[0];
    const float* fl0 = (const float*)d_in[1];
    const float* im1 = (const float*)d_in[2];
    const float* fl1 = (const float*)d_in[3];
    const float* im2 = (const float*)d_in[4];
    const float* fl2 = (const float*)d_in[5];
    const float* im3 = (const float*)d_in[6];
    const float* fl3 = (const float*)d_in[7];
    float* out = (float*)d_out;

    k1_transpose_all<<<43520, 256>>>(im0, im1, im2, im3);
    k2_gather_all<<<43692, 256>>>(fl0, fl1, fl2, fl3, out);
}

// round 17
// speedup vs baseline: 1.0162x; 1.0064x over previous
#include <cuda_runtime.h>
#include <cuda_fp16.h>

// Channel-last fp16 copies of all 4 img tensors.
// Half-element offsets: s512: 0 | s256: 67,108,864 | s128: 83,886,080 |
// s64: 88,080,384. Total 89,128,960 halfs.
__device__ __half g_timg[89128960];

// Per-scale block counts (256 threads, 2 threads/pixel, 128 px/block):
//   s512: 32768 (2048/batch) | s256: 8192 | s128: 2048 | s64: 512

// ---------------------------------------------------------------------------
// Transpose [B,C,H,W] fp32 -> [B,H,W,C] fp16 (proven path, unchanged).
// ---------------------------------------------------------------------------
template <unsigned LG>
__device__ __forceinline__ void do_transpose(const float* __restrict__ img,
                                             __half* __restrict__ timg,
                                             unsigned bx) {
    const unsigned t  = bx * 256u + threadIdx.x;
    const unsigned g  = t & 1u;
    const unsigned p  = t >> 1;
    constexpr unsigned HW = 1u << (2u * LG);
    const unsigned b  = p >> (2u * LG);

    const float* src = img + (size_t)p + (size_t)(b * 15u + g * 8u) * HW;
    float v[8];
#pragma unroll
    for (int k = 0; k < 8; k++) v[k] = __ldcs(src + (size_t)k * HW);

    __half2 h0 = __floats2half2_rn(v[0], v[1]);
    __half2 h1 = __floats2half2_rn(v[2], v[3]);
    __half2 h2 = __floats2half2_rn(v[4], v[5]);
    __half2 h3 = __floats2half2_rn(v[6], v[7]);
    uint4 o;
    o.x = *reinterpret_cast<unsigned*>(&h0);
    o.y = *reinterpret_cast<unsigned*>(&h1);
    o.z = *reinterpret_cast<unsigned*>(&h2);
    o.w = *reinterpret_cast<unsigned*>(&h3);
    reinterpret_cast<uint4*>(timg)[t] = o;
}

// ---------------------------------------------------------------------------
// Gather (proven R14 path + flow-shuffle dedup): 2 threads per pixel
// (8 channels each). The pair threads (adjacent lanes, same pixel) split the
// flow load -- even lane loads flow ch0, odd lane loads flow ch1 -- and
// exchange via one shfl_xor(1). Halves flow LDG instructions/wavefronts.
// Corners: branchless clamped weights, 4 unconditional LDG.128 (unchanged).
// Streaming __stcs stores on out (unchanged).
//   x = (i-1) + flow_ch0 * 0.5*(W-1)   (width coord)
//   y = (j-1) + flow_ch1 * 0.5*(H-1)   (height coord)
// ---------------------------------------------------------------------------
template <unsigned LG>
__device__ __forceinline__ void do_gather(const float* __restrict__ flow,
                                          const __half* __restrict__ timg,
                                          float* __restrict__ outp,
                                          unsigned bx) {
    const unsigned t     = bx * 256u + threadIdx.x;
    const unsigned chalf = t & 1u;
    const unsigned p     = t >> 1;
    constexpr unsigned W  = 1u << LG;
    constexpr unsigned HW = 1u << (2u * LG);
    constexpr int      Wi = (int)W;
    const unsigned j   = p & (W - 1u);
    const unsigned i   = (p >> LG) & (W - 1u);
    const unsigned b   = p >> (2u * LG);
    const unsigned pix = p & (HW - 1u);

    // Flow dedup: lane parity (== chalf, since t maps 1:1 to lanes) selects
    // which flow channel this thread loads; pair-exchange supplies the other.
    const float fmine = __ldcs(flow + (size_t)(b * 2u + chalf) * HW + pix);
    const float fother = __shfl_xor_sync(0xFFFFFFFFu, fmine, 1);
    const float f0 = chalf ? fother : fmine;   // flow ch0
    const float f1 = chalf ? fmine : fother;   // flow ch1

    constexpr float sc = 0.5f * (float)(W - 1u);
    const float x = (float)((int)i - 1) + f0 * sc;   // width coord
    const float y = (float)((int)j - 1) + f1 * sc;   // height coord

    const float x0f = floorf(x);
    const float y0f = floorf(y);
    const int x0 = (int)x0f, x1 = x0 + 1;
    const int y0 = (int)y0f, y1 = y0 + 1;
    const float fx = x - x0f, fy = y - y0f;

    const float wx1 = (x1 >= 0 && x1 < Wi) ? fx        : 0.0f;
    const float wx0 = (x0 >= 0 && x0 < Wi) ? 1.0f - fx : 0.0f;
    const float wy1 = (y1 >= 0 && y1 < Wi) ? fy        : 0.0f;
    const float wy0 = (y0 >= 0 && y0 < Wi) ? 1.0f - fy : 0.0f;

    const unsigned x0c = (unsigned)min(max(x0, 0), Wi - 1);
    const unsigned x1c = (unsigned)min(max(x1, 0), Wi - 1);
    const unsigned y0c = (unsigned)min(max(y0, 0), Wi - 1);
    const unsigned y1c = (unsigned)min(max(y1, 0), Wi - 1);

    const uint4* base = reinterpret_cast<const uint4*>(timg)
                        + (size_t)(b * HW) * 2u + chalf;
    const uint4 r00 = __ldg(base + (size_t)(y0c * W + x0c) * 2u);
    const uint4 r01 = __ldg(base + (size_t)(y0c * W + x1c) * 2u);
    const uint4 r10 = __ldg(base + (size_t)(y1c * W + x0c) * 2u);
    const uint4 r11 = __ldg(base + (size_t)(y1c * W + x1c) * 2u);

    const float w00 = wy0 * wx0, w01 = wy0 * wx1;
    const float w10 = wy1 * wx0, w11 = wy1 * wx1;

    float acc[8];
    const unsigned c00[4] = {r00.x, r00.y, r00.z, r00.w};
    const unsigned c01[4] = {r01.x, r01.y, r01.z, r01.w};
    const unsigned c10[4] = {r10.x, r10.y, r10.z, r10.w};
    const unsigned c11[4] = {r11.x, r11.y, r11.z, r11.w};
#pragma unroll
    for (int q = 0; q < 4; q++) {
        float2 v00 = __half22float2(*reinterpret_cast<const __half2*>(&c00[q]));
        float2 v01 = __half22float2(*reinterpret_cast<const __half2*>(&c01[q]));
        float2 v10 = __half22float2(*reinterpret_cast<const __half2*>(&c10[q]));
        float2 v11 = __half22float2(*reinterpret_cast<const __half2*>(&c11[q]));
        acc[2 * q + 0] = w00 * v00.x + w01 * v01.x + w10 * v10.x + w11 * v11.x;
        acc[2 * q + 1] = w00 * v00.y + w01 * v01.y + w10 * v10.y + w11 * v11.y;
    }

    // out layout [B,C,H,W]; this thread's channels are [chalf*8, chalf*8+8).
    float* ob = outp + (size_t)(b * 16u + chalf * 8u) * HW + pix;
#pragma unroll
    for (int q = 0; q < 8; q++) {
        __stcs(ob + (size_t)q * HW, acc[q]);
    }
}

// Small-scale dispatchers (10752 blocks: s256 [0,8192) | s128 [8192,10240) |
// s64 [10240,10752)).
__device__ __forceinline__ void tsmall(unsigned bx,
                                       const float* im1, const float* im2,
                                       const float* im3) {
    if (bx < 8192u)       do_transpose<8>(im1, g_timg + 67108864u, bx);
    else if (bx < 10240u) do_transpose<7>(im2, g_timg + 83886080u, bx - 8192u);
    else                  do_transpose<6>(im3, g_timg + 88080384u, bx - 10240u);
}
__device__ __forceinline__ void gsmall(unsigned bx,
                                       const float* fl1, const float* fl2,
                                       const float* fl3, float* out) {
    if (bx < 8192u)       do_gather<8>(fl1, g_timg + 67108864u, out + 67108864u, bx);
    else if (bx < 10240u) do_gather<7>(fl2, g_timg + 83886080u, out + 83886080u, bx - 8192u);
    else                  do_gather<6>(fl3, g_timg + 88080384u, out + 88080384u, bx - 10240u);
}

// ---------------------------------------------------------------------------
// K1 (unchanged): ALL transposes. T512 blocks [0,32768) ascending, small
// transposes last -> small timg + late s512 batches L2-hot at K2 start.
// Grid = 43520. Pure DRAM streaming.
// ---------------------------------------------------------------------------
__global__ void k1_transpose_all(const float* __restrict__ im0,
                                 const float* __restrict__ im1,
                                 const float* __restrict__ im2,
                                 const float* __restrict__ im3) {
    const unsigned bx = blockIdx.x;
    if (bx < 32768u) do_transpose<9>(im0, g_timg, bx);
    else             tsmall(bx - 32768u, im1, im2, im3);
}

// ---------------------------------------------------------------------------
// K2 (unchanged schedule): ALL gathers, 3:1 interleave (G512 : small). G512
// in DESCENDING batch order (batch 15 first = most recently transposed,
// L2-resident). 2048 blocks per batch. grps = 10923, grid = 43692.
// ---------------------------------------------------------------------------
__global__ void k2_gather_all(const float* __restrict__ fl0,
                              const float* __restrict__ fl1,
                              const float* __restrict__ fl2,
                              const float* __restrict__ fl3,
                              float* __restrict__ out) {
    const unsigned bx   = blockIdx.x;
    const unsigned lane = bx & 3u;
    const unsigned grp  = bx >> 2;
    if (lane < 3u) {
        const unsigned gbx = grp * 3u + lane;
        if (gbx < 32768u) {
            const unsigned bb  = 15u - (gbx >> 11);   // descending batch
            const unsigned blk = gbx & 2047u;
            do_gather<9>(fl0, g_timg, out, bb * 2048u + blk);
        }
    } else {
        if (grp < 10752u) gsmall(grp, fl1, fl2, fl3, out);
    }
}

// ---------------------------------------------------------------------------
// Inputs (metadata order): img0, flow0, img1, flow1, img2, flow2, img3, flow3.
// ---------------------------------------------------------------------------
extern "C" void kernel_launch(void* const* d_in, const int* in_sizes, int n_in,
                              void* d_out, int out_size) {
    (void)in_sizes; (void)n_in; (void)out_size;
    const float* im0 = (const float*)d_in[0];
    const float* fl0 = (const float*)d_in[1];
    const float* im1 = (const float*)d_in[2];
    const float* fl1 = (const float*)d_in[3];
    const float* im2 = (const float*)d_in[4];
    const float* fl2 = (const float*)d_in[5];
    const float* im3 = (const float*)d_in[6];
    const float* fl3 = (const float*)d_in[7];
    float* out = (float*)d_out;

    k1_transpose_all<<<43520, 256>>>(im0, im1, im2, im3);
    k2_gather_all<<<43692, 256>>>(fl0, fl1, fl2, fl3, out);
}